// round 1
// baseline (speedup 1.0000x reference)
#include <cuda_runtime.h>
#include <cstdint>

// SpatialCoherenceConv reduced form:
//   result = (1/B) * sum_{b,c,h,w} [ (81 + cw(h)*cw(w)) * x^2 - 2 * x * box9(x) ]
// where box9 = zero-padded 9x9 box sum (separable), cw(i) = #windows covering i.

#define HH 512
#define WW 512
#define KRAD 4
#define CPT 4            // columns per thread (float4)
#define TPB 128          // threads per block -> covers 512 columns
#define STRIP 128        // rows per block
#define TILES (HH / STRIP)   // 4 row tiles per plane

__device__ double g_partials[4096];

__device__ __forceinline__ float cw_of(int i, int n) {
    int l = (i < KRAD) ? (KRAD - i) : 0;
    int r = (i > n - 1 - KRAD) ? (i - (n - 1 - KRAD)) : 0;
    return (float)(2 * KRAD + 1 - l - r);
}

__global__ __launch_bounds__(TPB) void scc_main_kernel(const float* __restrict__ img) {
    const int bid   = blockIdx.x;
    const int plane = bid / TILES;
    const int tile  = bid % TILES;
    const int r0    = tile * STRIP;
    const float* __restrict__ P = img + (size_t)plane * (HH * WW);

    const int tid = threadIdx.x;
    const int c0  = tid * CPT;

    __shared__ float ring[9][WW];        // 9-row history; columns private per thread
    __shared__ float vsbuf[2][WW + 2 * KRAD]; // vertical sums + zero halos, double buffered
    __shared__ double sred[4];

    // zero the horizontal halos once (never overwritten)
    if (tid < 16) {
        int b = tid >> 3;
        int i = tid & 7;
        int idx = (i < 4) ? i : (WW + i);  // 0..3 and 516..519
        vsbuf[b][idx] = 0.0f;
    }

    // per-thread column weights cw(c)
    float wc0 = cw_of(c0 + 0, WW);
    float wc1 = cw_of(c0 + 1, WW);
    float wc2 = cw_of(c0 + 2, WW);
    float wc3 = cw_of(c0 + 3, WW);

    // prefill ring with rows r0-4 .. r0+4, build vertical running sum
    float4 vsum = make_float4(0.f, 0.f, 0.f, 0.f);
    #pragma unroll
    for (int i = 0; i < 9; i++) {
        int rr = r0 - KRAD + i;
        int slot = (rr + 9) % 9;           // rr >= -4
        float4 v = make_float4(0.f, 0.f, 0.f, 0.f);
        if (rr >= 0 && rr < HH) v = *(const float4*)(P + (size_t)rr * WW + c0);
        *(float4*)&ring[slot][c0] = v;
        vsum.x += v.x; vsum.y += v.y; vsum.z += v.z; vsum.w += v.w;
    }

    int cs  = r0 % 9;            // ring slot holding current center row r
    int ns  = (r0 + 5) % 9;      // slot to be replaced (row r-4 -> row r+5)
    int buf = 0;

    float acc0 = 0.f, acc1 = 0.f, acc2 = 0.f, acc3 = 0.f;

    #pragma unroll 2
    for (int r = r0; r < r0 + STRIP; r++) {
        // publish vertical sums for this row
        *(float4*)&vsbuf[buf][KRAD + c0] = vsum;
        __syncthreads();

        // horizontal 9-sum via halo reads + slide
        float4 L = *(const float4*)&vsbuf[buf][c0];              // vs[c0-4 .. c0-1]
        float4 R = *(const float4*)&vsbuf[buf][KRAD + c0 + 4];   // vs[c0+4 .. c0+7]
        float4 xc = *(const float4*)&ring[cs][c0];               // center row values

        float vsum_all = (vsum.x + vsum.y) + (vsum.z + vsum.w);
        float h0 = ((L.x + L.y) + (L.z + L.w)) + vsum_all + R.x;
        float h1 = h0 - L.x + R.y;
        float h2 = h1 - L.y + R.z;
        float h3 = h2 - L.z + R.w;

        float wr = cw_of(r, HH);
        float cf0 = fmaf(wr, wc0, 81.f);
        float cf1 = fmaf(wr, wc1, 81.f);
        float cf2 = fmaf(wr, wc2, 81.f);
        float cf3 = fmaf(wr, wc3, 81.f);

        // acc += x * (coef*x - 2*h)
        float v0 = fmaf(cf0, xc.x, -(h0 + h0));
        float v1 = fmaf(cf1, xc.y, -(h1 + h1));
        float v2 = fmaf(cf2, xc.z, -(h2 + h2));
        float v3 = fmaf(cf3, xc.w, -(h3 + h3));
        acc0 = fmaf(xc.x, v0, acc0);
        acc1 = fmaf(xc.y, v1, acc1);
        acc2 = fmaf(xc.z, v2, acc2);
        acc3 = fmaf(xc.w, v3, acc3);

        // slide vertical window: add row r+5, drop row r-4
        int rr = r + 5;
        float4 nv = make_float4(0.f, 0.f, 0.f, 0.f);
        if (rr < HH) nv = *(const float4*)(P + (size_t)rr * WW + c0);
        float4 ov = *(const float4*)&ring[ns][c0];
        vsum.x += nv.x - ov.x;
        vsum.y += nv.y - ov.y;
        vsum.z += nv.z - ov.z;
        vsum.w += nv.w - ov.w;
        *(float4*)&ring[ns][c0] = nv;

        cs = (cs == 8) ? 0 : cs + 1;
        ns = (ns == 8) ? 0 : ns + 1;
        buf ^= 1;
    }

    // block reduction (double, fixed order -> deterministic)
    double d = (double)acc0 + (double)acc1 + (double)acc2 + (double)acc3;
    #pragma unroll
    for (int off = 16; off > 0; off >>= 1)
        d += __shfl_down_sync(0xffffffffu, d, off);

    int warp = tid >> 5;
    int lane = tid & 31;
    if (lane == 0) sred[warp] = d;
    __syncthreads();
    if (tid == 0)
        g_partials[bid] = (sred[0] + sred[1]) + (sred[2] + sred[3]);
}

__global__ void scc_reduce_kernel(float* __restrict__ out, int nblocks, double inv_b) {
    __shared__ double sred[8];
    double d = 0.0;
    for (int i = threadIdx.x; i < nblocks; i += blockDim.x)
        d += g_partials[i];
    #pragma unroll
    for (int off = 16; off > 0; off >>= 1)
        d += __shfl_down_sync(0xffffffffu, d, off);
    int warp = threadIdx.x >> 5;
    int lane = threadIdx.x & 31;
    if (lane == 0) sred[warp] = d;
    __syncthreads();
    if (threadIdx.x == 0) {
        double tot = 0.0;
        int nw = (blockDim.x + 31) >> 5;
        for (int w = 0; w < nw; w++) tot += sred[w];
        out[0] = (float)(tot * inv_b);
    }
}

extern "C" void kernel_launch(void* const* d_in, const int* in_sizes, int n_in,
                              void* d_out, int out_size) {
    const float* img = (const float*)d_in[0];
    float* out = (float*)d_out;

    int nplanes = in_sizes[0] / (HH * WW);   // B*C = 256
    int batch   = nplanes / 32;              // C = 32 -> B = 8
    int nblocks = nplanes * TILES;           // 1024

    scc_main_kernel<<<nblocks, TPB>>>(img);
    scc_reduce_kernel<<<1, 256>>>(out, nblocks, 1.0 / (double)batch);
}